// round 7
// baseline (speedup 1.0000x reference)
#include <cuda_runtime.h>
#include <cstdint>

// ============================================================================
// Problem constants
// ============================================================================
#define M_TOTAL   32768
#define N_TOTAL   1024
#define K_TOTAL   1024
#define THRESH    0.05f

// ---- M split: mma rows [0, M_MMA), dp4a rows [M_MMA, 32768)
#define M_MMA     21760                 // 170 tiles of 128
#define M_DP      11008                 // 172 tiles of 64
#define MMA_MT    170
#define DP_MT     172

// ---- fused CTA tiling: N tile 64 shared; mma 128M, dp 64M
#define TILE_K    64
#define NUM_KC    (K_TOTAL / TILE_K)    // 16
#define STAGES    3
#define PITCH     80                    // 64B data + 16B pad
#define A_MMA_OFF 0
#define A_DP_OFF  (128 * PITCH)         // 10240
#define B_OFF     (A_DP_OFF + 64 * PITCH)  // 15360
#define STAGE_BYTES (B_OFF + 64 * PITCH)   // 20480
#define SMEM_TOTAL  (STAGES * STAGE_BYTES) // 61440

#define N_TILES   (N_TOTAL / 64)        // 16
#define TOTAL_CTAS (DP_MT * N_TILES)    // 2752 (mma part idle-stores for mt>=170)

// ============================================================================
// Scratch (device globals — no runtime allocation)
// ============================================================================
__device__ int8_t g_xq[(size_t)M_TOTAL * K_TOTAL];   // 32 MiB
__device__ int8_t g_wq[(size_t)N_TOTAL * K_TOTAL];   // 1 MiB

// ============================================================================
// Helpers
// ============================================================================
__device__ __forceinline__ uint32_t smem_u32(const void* p) {
    uint32_t a;
    asm("{ .reg .u64 t; cvta.to.shared.u64 t, %1; cvt.u32.u64 %0, t; }"
        : "=r"(a) : "l"(p));
    return a;
}

#define CP_ASYNC16(dst_u32, gsrc) \
    asm volatile("cp.async.cg.shared.global [%0], [%1], 16;" \
                 :: "r"(dst_u32), "l"(gsrc) : "memory")
#define CP_ASYNC_COMMIT() asm volatile("cp.async.commit_group;" ::: "memory")
#define CP_ASYNC_WAIT(n)  asm volatile("cp.async.wait_group %0;" :: "n"(n) : "memory")

__device__ __forceinline__ void mma_s8(int* c, const uint32_t* a, const uint32_t* b) {
    asm volatile(
        "mma.sync.aligned.m16n8k32.row.col.s32.s8.s8.s32 "
        "{%0,%1,%2,%3}, {%4,%5,%6,%7}, {%8,%9}, {%0,%1,%2,%3};"
        : "+r"(c[0]), "+r"(c[1]), "+r"(c[2]), "+r"(c[3])
        : "r"(a[0]), "r"(a[1]), "r"(a[2]), "r"(a[3]), "r"(b[0]), "r"(b[1]));
}

__device__ __forceinline__ void ldsm_x4(uint32_t* r, uint32_t addr) {
    asm volatile("ldmatrix.sync.aligned.m8n8.x4.shared.b16 {%0,%1,%2,%3}, [%4];"
        : "=r"(r[0]), "=r"(r[1]), "=r"(r[2]), "=r"(r[3]) : "r"(addr));
}

__device__ __forceinline__ int8_t tq(float v) {
    return (fabsf(v) < THRESH) ? (int8_t)0 : (v > 0.f ? (int8_t)1 : (int8_t)-1);
}

// ============================================================================
// Prep: one kernel quantizes BOTH x and w (fp32 -> ternary int8, 16/thread)
// ============================================================================
#define N16_X ((M_TOTAL * K_TOTAL) / 16)
#define N16_W ((N_TOTAL * K_TOTAL) / 16)
#define N16_TOTAL (N16_X + N16_W)

__global__ __launch_bounds__(256) void prep_kernel(
    const float* __restrict__ x, const float* __restrict__ w)
{
    int i = blockIdx.x * blockDim.x + threadIdx.x;
    if (i >= N16_TOTAL) return;
    const float4* src;
    int4* dst;
    if (i < N16_X) {
        src = (const float4*)x + i * 4;
        dst = (int4*)g_xq + i;
    } else {
        int j = i - N16_X;
        src = (const float4*)w + j * 4;
        dst = (int4*)g_wq + j;
    }
    int8_t r[16];
    #pragma unroll
    for (int j = 0; j < 4; j++) {
        float4 v = src[j];
        r[j * 4 + 0] = tq(v.x);
        r[j * 4 + 1] = tq(v.y);
        r[j * 4 + 2] = tq(v.z);
        r[j * 4 + 3] = tq(v.w);
    }
    *dst = *reinterpret_cast<int4*>(r);
}

// ============================================================================
// Fused GEMM CTA: 8 warps — warps 0-3 mma (128Mx64N), warps 4-7 dp4a (64Mx64N).
// One warp of each engine per SMSP -> tensor AND fma pipes busy on every SMSP.
// Shared B tile (same n0). 3-stage cp.async pipeline, barrier per K-chunk.
// ============================================================================
__global__ __launch_bounds__(256, 2) void ternary_gemm_kernel(float* __restrict__ out)
{
    extern __shared__ char smem[];
    const int tid  = threadIdx.x;
    const int lane = tid & 31;
    const int wid  = tid >> 5;

    const int c  = (int)blockIdx.x;
    const int n0 = (c & 15) * 64;
    const int mt = c >> 4;                      // 0..171
    const int mtm = (mt < MMA_MT) ? mt : (mt - MMA_MT);  // wrap for last 32 CTAs
    const bool mma_store = (mt < MMA_MT);
    const int m0_mma = mtm * 128;
    const int m0_dp  = M_MMA + mt * 64;

    const uint64_t xg = __cvta_generic_to_global(g_xq);
    const uint64_t wg = __cvta_generic_to_global(g_wq);
    const uint32_t sbase = smem_u32(smem);

    // ---- stage loader: 1024 x 16B chunks, 4 per thread
    auto load_stage = [&](int kc, int s) {
        uint32_t sb = sbase + s * STAGE_BYTES;
        uint32_t ko = (uint32_t)(kc * TILE_K);
        #pragma unroll
        for (int t = 0; t < 4; t++) {
            int i = tid + t * 256;
            if (i < 512) {                       // A_mma: 128 rows x 4 seg
                int row = i >> 2, seg = i & 3;
                uint64_t src = xg + (uint64_t)(m0_mma + row) * K_TOTAL + ko + seg * 16;
                CP_ASYNC16(sb + A_MMA_OFF + row * PITCH + seg * 16, src);
            } else if (i < 768) {                // A_dp: 64 rows x 4 seg
                int j = i - 512;
                int row = j >> 2, seg = j & 3;
                uint64_t src = xg + (uint64_t)(m0_dp + row) * K_TOTAL + ko + seg * 16;
                CP_ASYNC16(sb + A_DP_OFF + row * PITCH + seg * 16, src);
            } else {                             // B: 64 rows x 4 seg
                int j = i - 768;
                int row = j >> 2, seg = j & 3;
                uint64_t src = wg + (uint64_t)(n0 + row) * K_TOTAL + ko + seg * 16;
                CP_ASYNC16(sb + B_OFF + row * PITCH + seg * 16, src);
            }
        }
        CP_ASYNC_COMMIT();
    };

    // ---- per-engine state
    // mma engine (warps 0-3): warp tile 32M x 64N
    const int g8 = lane >> 3, t8 = lane & 7;
    const uint32_t a_lane = (uint32_t)((t8 + ((g8 & 1) << 3)) * PITCH + ((g8 >> 1) << 4));
    const uint32_t b_lane = (uint32_t)((t8 + ((g8 >> 1) << 3)) * PITCH + ((g8 & 1) << 4));

    int acc_m[2][8][4];                          // mma accumulators
    int acc_d[4][8];                             // dp accumulators (4M x 8N)
    #pragma unroll
    for (int mi = 0; mi < 2; mi++)
        #pragma unroll
        for (int ni = 0; ni < 8; ni++)
            #pragma unroll
            for (int q = 0; q < 4; q++) acc_m[mi][ni][q] = 0;
    #pragma unroll
    for (int i = 0; i < 4; i++)
        #pragma unroll
        for (int j = 0; j < 8; j++) acc_d[i][j] = 0;

    // dp engine (warps 4-7): 128 threads, thread tile 4M x 8N
    const int wtid = tid - 128;                  // 0..127 for dp warps
    const int tx = wtid & 7;                     // N group (8 cols)
    const int ty = wtid >> 3;                    // M group (4 rows)

    load_stage(0, 0);
    load_stage(1, 1);

    for (int kc = 0; kc < NUM_KC; kc++) {
        if (kc + STAGES - 1 < NUM_KC) CP_ASYNC_WAIT(STAGES - 2);
        else                          CP_ASYNC_WAIT(0);
        __syncthreads();

        const uint32_t stage = sbase + (kc % STAGES) * STAGE_BYTES;

        if (wid < 4) {
            // ================= mma engine =================
            const uint32_t sa  = stage + A_MMA_OFF + (uint32_t)(wid * 32) * PITCH + a_lane;
            const uint32_t sbB = stage + B_OFF + b_lane;
            #pragma unroll
            for (int kk = 0; kk < 2; kk++) {
                const uint32_t ko = (uint32_t)(kk * 32);
                uint32_t a[2][4];
                ldsm_x4(a[0], sa + ko);
                ldsm_x4(a[1], sa + 16 * PITCH + ko);
                uint32_t b[4][4];
                #pragma unroll
                for (int p = 0; p < 4; p++)
                    ldsm_x4(b[p], sbB + (uint32_t)(p * 16) * PITCH + ko);
                #pragma unroll
                for (int mi = 0; mi < 2; mi++)
                    #pragma unroll
                    for (int ni = 0; ni < 8; ni++)
                        mma_s8(acc_m[mi][ni], a[mi], &b[ni >> 1][(ni & 1) * 2]);
            }
        } else {
            // ================= dp4a engine =================
            const char* aS = smem + (kc % STAGES) * STAGE_BYTES + A_DP_OFF + (ty * 4) * PITCH;
            const char* bS = smem + (kc % STAGES) * STAGE_BYTES + B_OFF + (tx * 8) * PITCH;
            #pragma unroll
            for (int wgp = 0; wgp < 4; wgp++) {  // 4 x 16B K-groups
                int4 a[4], b[8];
                #pragma unroll
                for (int i = 0; i < 4; i++)
                    a[i] = *(const int4*)(aS + i * PITCH + wgp * 16);
                #pragma unroll
                for (int j = 0; j < 8; j++)
                    b[j] = *(const int4*)(bS + j * PITCH + wgp * 16);
                #pragma unroll
                for (int i = 0; i < 4; i++)
                    #pragma unroll
                    for (int j = 0; j < 8; j++) {
                        int s = acc_d[i][j];
                        s = __dp4a(a[i].x, b[j].x, s);
                        s = __dp4a(a[i].y, b[j].y, s);
                        s = __dp4a(a[i].z, b[j].z, s);
                        s = __dp4a(a[i].w, b[j].w, s);
                        acc_d[i][j] = s;
                    }
            }
        }
        __syncthreads();   // all reads of this stage done before refill

        if (kc + STAGES - 1 < NUM_KC)
            load_stage(kc + STAGES - 1, (kc + STAGES - 1) % STAGES);
    }

    // ---- Epilogues (int32 -> fp32 exact, |acc| <= 1024)
    if (wid < 4) {
        if (mma_store) {
            #pragma unroll
            for (int mi = 0; mi < 2; mi++) {
                const int r = m0_mma + wid * 32 + mi * 16 + (lane >> 2);
                #pragma unroll
                for (int ni = 0; ni < 8; ni++) {
                    const int cc = n0 + ni * 8 + (lane & 3) * 2;
                    float2 v0 = make_float2((float)acc_m[mi][ni][0], (float)acc_m[mi][ni][1]);
                    float2 v1 = make_float2((float)acc_m[mi][ni][2], (float)acc_m[mi][ni][3]);
                    *(float2*)(out + (size_t)r * N_TOTAL + cc)       = v0;
                    *(float2*)(out + (size_t)(r + 8) * N_TOTAL + cc) = v1;
                }
            }
        }
    } else {
        #pragma unroll
        for (int i = 0; i < 4; i++) {
            const int r = m0_dp + ty * 4 + i;
            float4 v0, v1;
            v0.x = (float)acc_d[i][0]; v0.y = (float)acc_d[i][1];
            v0.z = (float)acc_d[i][2]; v0.w = (float)acc_d[i][3];
            v1.x = (float)acc_d[i][4]; v1.y = (float)acc_d[i][5];
            v1.z = (float)acc_d[i][6]; v1.w = (float)acc_d[i][7];
            float* p = out + (size_t)r * N_TOTAL + n0 + tx * 8;
            *(float4*)(p)     = v0;
            *(float4*)(p + 4) = v1;
        }
    }
}

// ============================================================================
// Launch (2 launches per call -> ncu -s5 lands on the GEMM)
// ============================================================================
extern "C" void kernel_launch(void* const* d_in, const int* in_sizes, int n_in,
                              void* d_out, int out_size)
{
    const float* x = (const float*)d_in[0];
    const float* w = (const float*)d_in[1];
    float* out = (float*)d_out;

    prep_kernel<<<(N16_TOTAL + 255) / 256, 256>>>(x, w);

    static bool attr_set = false;
    if (!attr_set) {
        cudaFuncSetAttribute(ternary_gemm_kernel,
                             cudaFuncAttributeMaxDynamicSharedMemorySize, SMEM_TOTAL);
        attr_set = true;
    }
    ternary_gemm_kernel<<<TOTAL_CTAS, 256, SMEM_TOTAL>>>(out);
}

// round 8
// speedup vs baseline: 2.4220x; 2.4220x over previous
#include <cuda_runtime.h>
#include <cstdint>

// ============================================================================
// Problem constants
// ============================================================================
#define M_TOTAL   32768
#define N_TOTAL   1024
#define K_TOTAL   1024
#define THRESH    0.05f

// ---- M split: mma rows [0, M_MMA), popc rows [M_MMA, 32768)
#define M_MMA     16384
#define M_POPC    16384
#define NWORDS    32                    // K/32 packed words

// ---- mma engine tiling (threads 0-255): 128M x 128N, 3-stage cp.async
#define TILE_M    128
#define TILE_N    128
#define TILE_K    64
#define NUM_KC    (K_TOTAL / TILE_K)    // 16
#define STAGES    3
#define PITCH     80
#define STAGE_BYTES ((TILE_M + TILE_N) * PITCH)   // 20480
#define SM_MMA_BYTES (STAGES * STAGE_BYTES)       // 61440

// ---- popc engine (threads 256-511): 128M x 128N, full K resident
#define SM_PX_OFF  SM_MMA_BYTES                   // x tile: 32 words x 128 rows x 8B = 32KB
#define SM_PW_OFF  (SM_PX_OFF + 32768)            // w tile: 32 words x 128 cols x 8B = 32KB
#define SMEM_TOTAL (SM_PW_OFF + 32768)            // 126976

#define N_TILES   8                     // 1024 / 128
#define M_TILES   128                   // 16384 / 128 (both engines)
#define TOTAL_CTAS (M_TILES * N_TILES)  // 1024

// ============================================================================
// Scratch (device globals — no runtime allocation)
// ============================================================================
__device__ int8_t g_xq[(size_t)M_MMA * K_TOTAL];     // 16 MiB (mma rows)
__device__ int8_t g_wq[(size_t)N_TOTAL * K_TOTAL];   // 1 MiB
__device__ uint2  g_xpk[NWORDS * M_POPC];            // 4 MiB, [w][r]
__device__ uint2  g_wpk[NWORDS * N_TOTAL];           // 256 KiB, [w][c]

// ============================================================================
// Helpers
// ============================================================================
__device__ __forceinline__ uint32_t smem_u32(const void* p) {
    uint32_t a;
    asm("{ .reg .u64 t; cvta.to.shared.u64 t, %1; cvt.u32.u64 %0, t; }"
        : "=r"(a) : "l"(p));
    return a;
}

#define CP_ASYNC16(dst_u32, gsrc) \
    asm volatile("cp.async.cg.shared.global [%0], [%1], 16;" \
                 :: "r"(dst_u32), "l"(gsrc) : "memory")
#define CP_ASYNC_COMMIT() asm volatile("cp.async.commit_group;" ::: "memory")
#define CP_ASYNC_WAIT(n)  asm volatile("cp.async.wait_group %0;" :: "n"(n) : "memory")
#define BAR_SYNC(id) asm volatile("bar.sync %0, 256;" :: "n"(id) : "memory")

__device__ __forceinline__ void mma_s8(int* c, const uint32_t* a, const uint32_t* b) {
    asm volatile(
        "mma.sync.aligned.m16n8k32.row.col.s32.s8.s8.s32 "
        "{%0,%1,%2,%3}, {%4,%5,%6,%7}, {%8,%9}, {%0,%1,%2,%3};"
        : "+r"(c[0]), "+r"(c[1]), "+r"(c[2]), "+r"(c[3])
        : "r"(a[0]), "r"(a[1]), "r"(a[2]), "r"(a[3]), "r"(b[0]), "r"(b[1]));
}

__device__ __forceinline__ void ldsm_x4(uint32_t* r, uint32_t addr) {
    asm volatile("ldmatrix.sync.aligned.m8n8.x4.shared.b16 {%0,%1,%2,%3}, [%4];"
        : "=r"(r[0]), "=r"(r[1]), "=r"(r[2]), "=r"(r[3]) : "r"(addr));
}

__device__ __forceinline__ int8_t tq(float v) {
    return (fabsf(v) < THRESH) ? (int8_t)0 : (v > 0.f ? (int8_t)1 : (int8_t)-1);
}

// ============================================================================
// Prep 1: int8 quantize — x rows [0, M_MMA) + all of w   (16 elems/thread)
// ============================================================================
#define N16_X ((M_MMA * K_TOTAL) / 16)       // 1,048,576
#define N16_W ((N_TOTAL * K_TOTAL) / 16)     // 65,536
#define N16_TOTAL (N16_X + N16_W)

__global__ __launch_bounds__(256) void prep_q_kernel(
    const float* __restrict__ x, const float* __restrict__ w)
{
    int i = blockIdx.x * blockDim.x + threadIdx.x;
    if (i >= N16_TOTAL) return;
    const float4* src;
    int4* dst;
    if (i < N16_X) { src = (const float4*)x + i * 4; dst = (int4*)g_xq + i; }
    else { int j = i - N16_X; src = (const float4*)w + j * 4; dst = (int4*)g_wq + j; }
    int8_t r[16];
    #pragma unroll
    for (int j = 0; j < 4; j++) {
        float4 v = src[j];
        r[j * 4 + 0] = tq(v.x); r[j * 4 + 1] = tq(v.y);
        r[j * 4 + 2] = tq(v.z); r[j * 4 + 3] = tq(v.w);
    }
    *dst = *reinterpret_cast<int4*>(r);
}

// ============================================================================
// Prep 2: bit-pack — x rows [M_MMA, 32768) -> g_xpk, w -> g_wpk
// thread t packs 32 floats into (e,n) masks; row-fastest for coalesced writes
// ============================================================================
#define PK_X (M_POPC * NWORDS)    // 524,288
#define PK_W (N_TOTAL * NWORDS)   // 32,768
#define PK_TOTAL (PK_X + PK_W)

__global__ __launch_bounds__(256) void prep_pk_kernel(
    const float* __restrict__ x, const float* __restrict__ w)
{
    int t = blockIdx.x * blockDim.x + threadIdx.x;
    if (t >= PK_TOTAL) return;
    const float4* p;
    uint2* dst;
    if (t < PK_X) {
        int r = t & (M_POPC - 1), wd = t >> 14;
        p = (const float4*)(x + (size_t)(M_MMA + r) * K_TOTAL + wd * 32);
        dst = g_xpk + (size_t)wd * M_POPC + r;
    } else {
        int j = t - PK_X;
        int c = j & (N_TOTAL - 1), wd = j >> 10;
        p = (const float4*)(w + (size_t)c * K_TOTAL + wd * 32);
        dst = g_wpk + (size_t)wd * N_TOTAL + c;
    }
    uint32_t e = 0, n = 0;
    #pragma unroll
    for (int j = 0; j < 8; j++) {
        float4 v = p[j];
        float f[4] = {v.x, v.y, v.z, v.w};
        #pragma unroll
        for (int q = 0; q < 4; q++) {
            uint32_t nz = (fabsf(f[q]) >= THRESH) ? 1u : 0u;
            uint32_t ng = (nz && f[q] < 0.f) ? 1u : 0u;
            e |= nz << (j * 4 + q);
            n |= ng << (j * 4 + q);
        }
    }
    *dst = make_uint2(e, n);
}

// ============================================================================
// Fused GEMM: 512 threads.
//   threads 0-255  : mma engine, rows [0,16384), tile 128x128, bar.sync 1
//   threads 256-511: popc engine, rows [16384,32768), tile 128x128, bar.sync 2
// Engines share NOTHING after launch — no cross-engine synchronization.
// ============================================================================
__global__ __launch_bounds__(512, 1) void ternary_gemm_kernel(float* __restrict__ out)
{
    extern __shared__ char smem[];
    const int tid = threadIdx.x;
    const int c = (int)blockIdx.x;
    const int n0 = (c & 7) * 128;
    const int mt = c >> 3;                 // 0..127
    const uint32_t sbase = smem_u32(smem);

    if (tid < 256) {
        // ===================== MMA ENGINE =====================
        const int lane = tid & 31;
        const int wid  = tid >> 5;         // 0..7
        const int wm   = wid & 3;
        const int wn   = wid >> 2;
        const int m0   = mt * TILE_M;

        const uint64_t xg = __cvta_generic_to_global(g_xq);
        const uint64_t wg = __cvta_generic_to_global(g_wq);

        const int g8 = lane >> 3, t8 = lane & 7;
        const uint32_t a_lane = (uint32_t)((t8 + ((g8 & 1) << 3)) * PITCH + ((g8 >> 1) << 4));
        const uint32_t b_lane = (uint32_t)((t8 + ((g8 >> 1) << 3)) * PITCH + ((g8 & 1) << 4));

        auto load_stage = [&](int kc, int s) {
            uint32_t sb = sbase + s * STAGE_BYTES;
            #pragma unroll
            for (int t = 0; t < 2; t++) {                  // A: 128 rows
                int i = tid + t * 256;
                int row = i >> 2, seg = i & 3;
                uint64_t src = xg + (uint64_t)(m0 + row) * K_TOTAL + kc * TILE_K + seg * 16;
                CP_ASYNC16(sb + row * PITCH + seg * 16, src);
            }
            #pragma unroll
            for (int t = 0; t < 2; t++) {                  // B: 128 rows
                int i = tid + t * 256;
                int row = i >> 2, seg = i & 3;
                uint64_t src = wg + (uint64_t)(n0 + row) * K_TOTAL + kc * TILE_K + seg * 16;
                CP_ASYNC16(sb + (TILE_M + row) * PITCH + seg * 16, src);
            }
            CP_ASYNC_COMMIT();
        };

        int acc[2][8][4];
        #pragma unroll
        for (int mi = 0; mi < 2; mi++)
            #pragma unroll
            for (int ni = 0; ni < 8; ni++)
                #pragma unroll
                for (int q = 0; q < 4; q++) acc[mi][ni][q] = 0;

        load_stage(0, 0);
        load_stage(1, 1);

        for (int kc = 0; kc < NUM_KC; kc++) {
            if (kc + STAGES - 1 < NUM_KC) CP_ASYNC_WAIT(STAGES - 2);
            else                          CP_ASYNC_WAIT(0);
            BAR_SYNC(1);

            const uint32_t stage = sbase + (kc % STAGES) * STAGE_BYTES;
            const uint32_t sa  = stage + (uint32_t)(wm * 32) * PITCH + a_lane;
            const uint32_t sbB = stage + (uint32_t)(TILE_M + wn * 64) * PITCH + b_lane;

            #pragma unroll
            for (int kk = 0; kk < 2; kk++) {
                const uint32_t ko = (uint32_t)(kk * 32);
                uint32_t a[2][4];
                ldsm_x4(a[0], sa + ko);
                ldsm_x4(a[1], sa + 16 * PITCH + ko);
                uint32_t b[4][4];
                #pragma unroll
                for (int p = 0; p < 4; p++)
                    ldsm_x4(b[p], sbB + (uint32_t)(p * 16) * PITCH + ko);
                #pragma unroll
                for (int mi = 0; mi < 2; mi++)
                    #pragma unroll
                    for (int ni = 0; ni < 8; ni++)
                        mma_s8(acc[mi][ni], a[mi], &b[ni >> 1][(ni & 1) * 2]);
            }
            BAR_SYNC(1);                  // reads of this stage done before refill

            if (kc + STAGES - 1 < NUM_KC)
                load_stage(kc + STAGES - 1, (kc + STAGES - 1) % STAGES);
        }

        #pragma unroll
        for (int mi = 0; mi < 2; mi++) {
            const int r = m0 + wm * 32 + mi * 16 + (lane >> 2);
            #pragma unroll
            for (int ni = 0; ni < 8; ni++) {
                const int cc = n0 + wn * 64 + ni * 8 + (lane & 3) * 2;
                float2 v0 = make_float2((float)acc[mi][ni][0], (float)acc[mi][ni][1]);
                float2 v1 = make_float2((float)acc[mi][ni][2], (float)acc[mi][ni][3]);
                *(float2*)(out + (size_t)r * N_TOTAL + cc)       = v0;
                *(float2*)(out + (size_t)(r + 8) * N_TOTAL + cc) = v1;
            }
        }
    } else {
        // ===================== POPC ENGINE =====================
        const int ptid = tid - 256;        // 0..255
        const int tx = ptid & 15;          // 16 col-groups
        const int ty = ptid >> 4;          // 16 row-groups
        const int m0 = mt * 128;           // within popc region

        const uint64_t xg = __cvta_generic_to_global(g_xpk);
        const uint64_t wg = __cvta_generic_to_global(g_wpk);
        const uint32_t px = sbase + SM_PX_OFF;   // [w][128 rows] uint2
        const uint32_t pw = sbase + SM_PW_OFF;   // [w][128 cols] uint2

        // Load x tile (32KB) + w tile (32KB), once.
        #pragma unroll
        for (int t = 0; t < 8; t++) {            // x: 2048 x 16B
            int i = ptid + t * 256;
            int wd = i >> 6, off = i & 63;       // off: 2 rows per 16B
            uint64_t src = xg + ((uint64_t)wd * M_POPC + m0 + off * 2) * 8;
            CP_ASYNC16(px + wd * 1024 + off * 16, src);
        }
        #pragma unroll
        for (int t = 0; t < 8; t++) {            // w: 2048 x 16B
            int i = ptid + t * 256;
            int wd = i >> 6, off = i & 63;
            uint64_t src = wg + ((uint64_t)wd * N_TOTAL + n0 + off * 2) * 8;
            CP_ASYNC16(pw + wd * 1024 + off * 16, src);
        }
        CP_ASYNC_COMMIT();
        CP_ASYNC_WAIT(0);
        BAR_SYNC(2);

        int acc[8][8];
        #pragma unroll
        for (int i = 0; i < 8; i++)
            #pragma unroll
            for (int j = 0; j < 8; j++) acc[i][j] = 0;

        const char* xb = smem + SM_PX_OFF + ty * 64;     // 8 rows x 8B
        const char* wb = smem + SM_PW_OFF + tx * 8;      // cols tx + 16j

        #pragma unroll 1
        for (int wd = 0; wd < NWORDS; wd++) {
            // 8 x-rows: 4 x LDS.128 (broadcast across tx)
            int4 xr[4];
            #pragma unroll
            for (int q = 0; q < 4; q++)
                xr[q] = *(const int4*)(xb + wd * 1024 + q * 16);
            // 8 w-cols (interleaved tx + 16j): 8 x LDS.64, conflict-free
            uint2 wc[8];
            #pragma unroll
            for (int j = 0; j < 8; j++)
                wc[j] = *(const uint2*)(wb + wd * 1024 + j * 128);

            #pragma unroll
            for (int i = 0; i < 8; i++) {
                const uint32_t xe = (i & 1) ? (uint32_t)xr[i >> 1].z : (uint32_t)xr[i >> 1].x;
                const uint32_t xn = (i & 1) ? (uint32_t)xr[i >> 1].w : (uint32_t)xr[i >> 1].y;
                #pragma unroll
                for (int j = 0; j < 8; j++) {
                    uint32_t t = xe & wc[j].x;
                    uint32_t d = t & (xn ^ wc[j].y);     // one LOP3
                    acc[i][j] += __popc(t) - 2 * __popc(d);
                }
            }
        }

        // Store: row M_MMA + m0 + ty*8 + i, col n0 + tx + 16j
        #pragma unroll
        for (int i = 0; i < 8; i++) {
            const int r = M_MMA + m0 + ty * 8 + i;
            float* prow = out + (size_t)r * N_TOTAL + n0 + tx;
            #pragma unroll
            for (int j = 0; j < 8; j++)
                prow[j * 16] = (float)acc[i][j];
        }
    }
}

// ============================================================================
// Launch (3 launches per call -> ncu -s5 lands on the GEMM)
// ============================================================================
extern "C" void kernel_launch(void* const* d_in, const int* in_sizes, int n_in,
                              void* d_out, int out_size)
{
    const float* x = (const float*)d_in[0];
    const float* w = (const float*)d_in[1];
    float* out = (float*)d_out;

    prep_q_kernel<<<(N16_TOTAL + 255) / 256, 256>>>(x, w);
    prep_pk_kernel<<<(PK_TOTAL + 255) / 256, 256>>>(x, w);

    static bool attr_set = false;
    if (!attr_set) {
        cudaFuncSetAttribute(ternary_gemm_kernel,
                             cudaFuncAttributeMaxDynamicSharedMemorySize, SMEM_TOTAL);
        attr_set = true;
    }
    ternary_gemm_kernel<<<TOTAL_CTAS, 512, SMEM_TOTAL>>>(out);
}